// round 8
// baseline (speedup 1.0000x reference)
#include <cuda_runtime.h>
#include <cuda_fp16.h>
#include <cuda_fp8.h>

// Inter_domain_loss as ONE persistent kernel, v2.
// 128 CTAs x 512 threads; each CTA holds 32 rows of fp8(G+eps) in SMEM.
// G read from DRAM once (P0); src/trg streamed in P2 overlapping smem work.
// Cross-CTA reductions via global partials + grid barriers (all CTAs resident:
// 1 CTA/SM at 164 KB smem, 128 <= 148 SMs).
// B=2048, N=4096. 2 reference Sinkhorn iterations (converged; fp8 validated
// at rel_err 2.7e-6 in R6/R7).

#define NN      4096
#define BB      2048
#define EPSV    1e-5f
#define NCTA    128
#define RPC     32            // G rows per CTA
#define MRPC    16            // src/trg rows per CTA
#define THREADS 512

// smem layout (dynamic)
#define SM_G8   0                          // 32*4096 fp8 = 131072
#define SM_VEC  131072                     // 4096 floats = 16384
#define SM_MS   (131072 + 16384)           // 4096 floats = 16384
#define SM_U    (131072 + 32768)           // 32 floats = 128
#define SM_W    (131072 + 32768 + 128)     // 16 floats = 64
#define SM_TOT  (131072 + 32768 + 128 + 64)

// Global scratch
__device__ float d_colpart[NCTA * NN];     // 2 MB
__device__ float d_meanpartS[NCTA * NN];   // 2 MB
__device__ float d_meanpartT[NCTA * NN];   // 2 MB
__device__ float d_v[NN];
__device__ float d_mean_src[NN];
__device__ float d_mean_trg[NN];
__device__ float d_ctapart[NCTA];
__device__ unsigned d_barcnt = 0;
__device__ unsigned d_bargen = 0;

// ---------------------------------------------------------------------------
__device__ __forceinline__ void grid_barrier() {
    __syncthreads();
    if (threadIdx.x == 0) {
        __threadfence();
        unsigned gen = atomicAdd(&d_bargen, 0u);
        unsigned old = atomicAdd(&d_barcnt, 1u);
        if (old == NCTA - 1) {
            atomicExch(&d_barcnt, 0u);
            atomicAdd(&d_bargen, 1u);
        } else {
            while (atomicAdd(&d_bargen, 0u) == gen) __nanosleep(32);
        }
    }
    __syncthreads();
}

__device__ __forceinline__ void fp8x4_to_f32(unsigned raw, float* f) {
    __half2_raw h0 = __nv_cvt_fp8x2_to_halfraw2((__nv_fp8x2_storage_t)(raw & 0xFFFFu), __NV_E4M3);
    __half2_raw h1 = __nv_cvt_fp8x2_to_halfraw2((__nv_fp8x2_storage_t)(raw >> 16), __NV_E4M3);
    float2 a = __half22float2(*reinterpret_cast<__half2*>(&h0));
    float2 b = __half22float2(*reinterpret_cast<__half2*>(&h1));
    f[0] = a.x; f[1] = a.y; f[2] = b.x; f[3] = b.y;
}

// ---------------------------------------------------------------------------
__global__ __launch_bounds__(THREADS, 1)
void k_fused(const float* __restrict__ src, const float* __restrict__ trg,
             const float* __restrict__ G, float* __restrict__ out) {
    extern __shared__ unsigned char smem[];
    unsigned char* g8  = smem + SM_G8;
    float*         vec = reinterpret_cast<float*>(smem + SM_VEC);
    float*         msm = reinterpret_cast<float*>(smem + SM_MS);
    float*         ush = reinterpret_cast<float*>(smem + SM_U);
    float*         wsc = reinterpret_cast<float*>(smem + SM_W);

    const int b  = blockIdx.x;
    const int t  = threadIdx.x;
    const int c  = t * 8;               // this thread's 8-column home slice
    const int r0 = b * RPC;
    const int w  = t >> 5, l = t & 31;

    // ===== P0: stream G slice -> fp8 smem + colsum0 partials (u0 = 1) =====
    {
        float acc[8] = {0.f, 0.f, 0.f, 0.f, 0.f, 0.f, 0.f, 0.f};
#pragma unroll 2
        for (int r = 0; r < RPC; ++r) {
            const float* gp = G + (size_t)(r0 + r) * NN + c;
            float4 a0 = *reinterpret_cast<const float4*>(gp);
            float4 a1 = *reinterpret_cast<const float4*>(gp + 4);
            float e[8] = {a0.x + EPSV, a0.y + EPSV, a0.z + EPSV, a0.w + EPSV,
                          a1.x + EPSV, a1.y + EPSV, a1.z + EPSV, a1.w + EPSV};
            uint2 packed;
            __nv_fp8x2_storage_t* p = reinterpret_cast<__nv_fp8x2_storage_t*>(&packed);
#pragma unroll
            for (int k = 0; k < 4; ++k) {
                p[k] = __nv_cvt_float2_to_fp8x2(make_float2(e[2 * k], e[2 * k + 1]),
                                                __NV_SATFINITE, __NV_E4M3);
                acc[2 * k]     += e[2 * k];
                acc[2 * k + 1] += e[2 * k + 1];
            }
            *reinterpret_cast<uint2*>(g8 + r * NN + c) = packed;
        }
        float* dst = d_colpart + (size_t)b * NN + c;
        *reinterpret_cast<float4*>(dst)     = make_float4(acc[0], acc[1], acc[2], acc[3]);
        *reinterpret_cast<float4*>(dst + 4) = make_float4(acc[4], acc[5], acc[6], acc[7]);
    }
    grid_barrier();

    // ===== P1: reduce colsum0 -> v1 =====
    {
        int col = b * 32 + (t >> 4);
        int s   = t & 15;
        float sum = 0.f;
#pragma unroll
        for (int k = 0; k < 8; ++k)
            sum += __ldcg(d_colpart + (size_t)(s * 8 + k) * NN + col);
#pragma unroll
        for (int off = 8; off; off >>= 1) sum += __shfl_down_sync(0xffffffffu, sum, off, 16);
        if (s == 0) d_v[col] = 1.0f / sum;
    }
    grid_barrier();

    // ===== P2: u1 per row + colsum(u1) partials + (overlap) mean partials =====
    {
        *reinterpret_cast<float4*>(vec + c)     = __ldcg(reinterpret_cast<const float4*>(d_v + c));
        *reinterpret_cast<float4*>(vec + c + 4) = __ldcg(reinterpret_cast<const float4*>(d_v + c + 4));
        __syncthreads();

        // u per row: 16 warps x 2 rows each
#pragma unroll
        for (int rr = 0; rr < 2; ++rr) {
            int r = w + rr * 16;
            const unsigned char* grow = g8 + r * NN;
            float a = 0.f;
#pragma unroll 8
            for (int k = 0; k < 32; ++k) {
                int j = l * 4 + k * 128;      // conflict-free stride
                unsigned raw = *reinterpret_cast<const unsigned*>(grow + j);
                float f[4];
                fp8x4_to_f32(raw, f);
                float4 vv = *reinterpret_cast<const float4*>(vec + j);
                a += f[0] * vv.x + f[1] * vv.y + f[2] * vv.z + f[3] * vv.w;
            }
#pragma unroll
            for (int off = 16; off; off >>= 1) a += __shfl_down_sync(0xffffffffu, a, off);
            if (l == 0) ush[r] = 1.0f / a;
        }
        __syncthreads();

        // colsum(u1) partials: thread owns 8 columns over 32 rows
        float acc[8] = {0.f, 0.f, 0.f, 0.f, 0.f, 0.f, 0.f, 0.f};
        for (int r = 0; r < RPC; ++r) {
            float u = ush[r];
            uint2 raw = *reinterpret_cast<const uint2*>(g8 + r * NN + c);
            float f[8];
            fp8x4_to_f32(raw.x, f);
            fp8x4_to_f32(raw.y, f + 4);
#pragma unroll
            for (int k = 0; k < 8; ++k) acc[k] += u * f[k];
        }
        float* dst = d_colpart + (size_t)b * NN + c;
        *reinterpret_cast<float4*>(dst)     = make_float4(acc[0], acc[1], acc[2], acc[3]);
        *reinterpret_cast<float4*>(dst + 4) = make_float4(acc[4], acc[5], acc[6], acc[7]);

        // mean partials (67 MB DRAM stream, overlapping other warps' smem work)
        float accS[8], accT[8];
#pragma unroll
        for (int k = 0; k < 8; ++k) { accS[k] = 0.f; accT[k] = 0.f; }
        int m0 = b * MRPC;
#pragma unroll 2
        for (int r = 0; r < MRPC; ++r) {
            const float* sp = src + (size_t)(m0 + r) * NN + c;
            const float* tp = trg + (size_t)(m0 + r) * NN + c;
            float4 s0 = *reinterpret_cast<const float4*>(sp);
            float4 s1 = *reinterpret_cast<const float4*>(sp + 4);
            float4 t0 = *reinterpret_cast<const float4*>(tp);
            float4 t1 = *reinterpret_cast<const float4*>(tp + 4);
            accS[0] += s0.x; accS[1] += s0.y; accS[2] += s0.z; accS[3] += s0.w;
            accS[4] += s1.x; accS[5] += s1.y; accS[6] += s1.z; accS[7] += s1.w;
            accT[0] += t0.x; accT[1] += t0.y; accT[2] += t0.z; accT[3] += t0.w;
            accT[4] += t1.x; accT[5] += t1.y; accT[6] += t1.z; accT[7] += t1.w;
        }
        float* dS = d_meanpartS + (size_t)b * NN + c;
        float* dT = d_meanpartT + (size_t)b * NN + c;
        *reinterpret_cast<float4*>(dS)     = make_float4(accS[0], accS[1], accS[2], accS[3]);
        *reinterpret_cast<float4*>(dS + 4) = make_float4(accS[4], accS[5], accS[6], accS[7]);
        *reinterpret_cast<float4*>(dT)     = make_float4(accT[0], accT[1], accT[2], accT[3]);
        *reinterpret_cast<float4*>(dT + 4) = make_float4(accT[4], accT[5], accT[6], accT[7]);
    }
    grid_barrier();

    // ===== P3: reduce -> v2 ; reduce means =====
    {
        int col = b * 32 + (t >> 4);
        int s   = t & 15;
        float sum = 0.f, sS = 0.f, sT = 0.f;
#pragma unroll
        for (int k = 0; k < 8; ++k) {
            int cta = s * 8 + k;
            sum += __ldcg(d_colpart   + (size_t)cta * NN + col);
            sS  += __ldcg(d_meanpartS + (size_t)cta * NN + col);
            sT  += __ldcg(d_meanpartT + (size_t)cta * NN + col);
        }
#pragma unroll
        for (int off = 8; off; off >>= 1) {
            sum += __shfl_down_sync(0xffffffffu, sum, off, 16);
            sS  += __shfl_down_sync(0xffffffffu, sS,  off, 16);
            sT  += __shfl_down_sync(0xffffffffu, sT,  off, 16);
        }
        if (s == 0) {
            d_v[col]        = 1.0f / sum;
            d_mean_src[col] = sS * (1.0f / (float)BB);
            d_mean_trg[col] = sT * (1.0f / (float)BB);
        }
    }
    grid_barrier();

    // ===== P4: exact row-normalize + loss; CTA partial =====
    {
        *reinterpret_cast<float4*>(vec + c)     = __ldcg(reinterpret_cast<const float4*>(d_v + c));
        *reinterpret_cast<float4*>(vec + c + 4) = __ldcg(reinterpret_cast<const float4*>(d_v + c + 4));
        *reinterpret_cast<float4*>(msm + c)     = __ldcg(reinterpret_cast<const float4*>(d_mean_src + c));
        *reinterpret_cast<float4*>(msm + c + 4) = __ldcg(reinterpret_cast<const float4*>(d_mean_src + c + 4));
        __syncthreads();

        float part = 0.f;
#pragma unroll
        for (int rr = 0; rr < 2; ++rr) {
            int r = w + rr * 16;
            float mt = __ldcg(d_mean_trg + r0 + r);
            const unsigned char* grow = g8 + r * NN;
            float at = 0.f, aw = 0.f;
#pragma unroll 8
            for (int k = 0; k < 32; ++k) {
                int j = l * 4 + k * 128;
                unsigned raw = *reinterpret_cast<const unsigned*>(grow + j);
                float f[4];
                fp8x4_to_f32(raw, f);
                float4 vv = *reinterpret_cast<const float4*>(vec + j);
                float4 mm = *reinterpret_cast<const float4*>(msm + j);
                float gv0 = f[0] * vv.x, gv1 = f[1] * vv.y;
                float gv2 = f[2] * vv.z, gv3 = f[3] * vv.w;
                at += gv0 + gv1 + gv2 + gv3;
                aw += fabsf(mt - mm.x) * gv0 + fabsf(mt - mm.y) * gv1
                    + fabsf(mt - mm.z) * gv2 + fabsf(mt - mm.w) * gv3;
            }
#pragma unroll
            for (int off = 16; off; off >>= 1) {
                at += __shfl_down_sync(0xffffffffu, at, off);
                aw += __shfl_down_sync(0xffffffffu, aw, off);
            }
            if (l == 0) part += aw / at;
        }
        if (l == 0) wsc[w] = part;
        __syncthreads();
        if (t == 0) {
            float s = 0.f;
#pragma unroll
            for (int k = 0; k < 16; ++k) s += wsc[k];
            d_ctapart[b] = s;
        }
    }
    grid_barrier();

    // ===== P5: CTA 0 reduces 128 partials =====
    if (b == 0 && t < 32) {
        float s = 0.f;
#pragma unroll
        for (int k = 0; k < NCTA / 32; ++k) s += __ldcg(d_ctapart + t + 32 * k);
#pragma unroll
        for (int off = 16; off; off >>= 1) s += __shfl_down_sync(0xffffffffu, s, off);
        if (t == 0) out[0] = s;
    }
}

// ---------------------------------------------------------------------------
extern "C" void kernel_launch(void* const* d_in, const int* in_sizes, int n_in,
                              void* d_out, int out_size) {
    (void)in_sizes; (void)n_in; (void)out_size;
    const float* src = (const float*)d_in[0];
    const float* trg = (const float*)d_in[1];
    const float* G   = (const float*)d_in[2];
    float* out = (float*)d_out;

    cudaFuncSetAttribute(k_fused, cudaFuncAttributeMaxDynamicSharedMemorySize, SM_TOT);
    k_fused<<<NCTA, THREADS, SM_TOT>>>(src, trg, G, out);
}

// round 9
// speedup vs baseline: 1.0012x; 1.0012x over previous
#include <cuda_runtime.h>
#include <cuda_fp16.h>
#include <cuda_fp8.h>

// Inter_domain_loss as ONE persistent kernel, v3 (warp-specialized P0).
// 128 CTAs x 512 threads; each CTA holds 32 rows of fp8(G+eps) in SMEM.
// P0: warps 0-7 stream G (fp8 smem + colsum0), warps 8-15 stream src/trg
// (mean partials) CONCURRENTLY -> one 134 MB DRAM phase.
// Cross-CTA reductions via global partials + grid barriers (all CTAs resident).
// 2 reference Sinkhorn iterations (fp8 validated at rel_err ~2.5e-6).

#define NN      4096
#define BB      2048
#define EPSV    1e-5f
#define NCTA    128
#define RPC     32            // G rows per CTA
#define MRPC    16            // src/trg rows per CTA
#define THREADS 512

// smem layout (dynamic)
#define SM_G8   0                          // 32*4096 fp8 = 131072
#define SM_VEC  131072                     // 4096 floats = 16384
#define SM_MS   (131072 + 16384)           // 4096 floats = 16384
#define SM_U    (131072 + 32768)           // 32 floats = 128
#define SM_W    (131072 + 32768 + 128)     // 16 floats = 64
#define SM_TOT  (131072 + 32768 + 128 + 64)

// Global scratch
__device__ float d_colpart[NCTA * NN];     // 2 MB
__device__ float d_meanpartS[NCTA * NN];   // 2 MB
__device__ float d_meanpartT[NCTA * NN];   // 2 MB
__device__ float d_v[NN];
__device__ float d_mean_src[NN];
__device__ float d_mean_trg[NN];
__device__ float d_ctapart[NCTA];
__device__ unsigned d_barcnt = 0;
__device__ unsigned d_bargen = 0;

// ---------------------------------------------------------------------------
__device__ __forceinline__ void grid_barrier() {
    __syncthreads();
    if (threadIdx.x == 0) {
        __threadfence();
        unsigned gen = atomicAdd(&d_bargen, 0u);
        unsigned old = atomicAdd(&d_barcnt, 1u);
        if (old == NCTA - 1) {
            atomicExch(&d_barcnt, 0u);
            atomicAdd(&d_bargen, 1u);
        } else {
            while (atomicAdd(&d_bargen, 0u) == gen) __nanosleep(32);
        }
    }
    __syncthreads();
}

__device__ __forceinline__ void fp8x4_to_f32(unsigned raw, float* f) {
    __half2_raw h0 = __nv_cvt_fp8x2_to_halfraw2((__nv_fp8x2_storage_t)(raw & 0xFFFFu), __NV_E4M3);
    __half2_raw h1 = __nv_cvt_fp8x2_to_halfraw2((__nv_fp8x2_storage_t)(raw >> 16), __NV_E4M3);
    float2 a = __half22float2(*reinterpret_cast<__half2*>(&h0));
    float2 b = __half22float2(*reinterpret_cast<__half2*>(&h1));
    f[0] = a.x; f[1] = a.y; f[2] = b.x; f[3] = b.y;
}

__device__ __forceinline__ float4 ldcs4(const float* p) {
    return __ldcs(reinterpret_cast<const float4*>(p));
}

// ---------------------------------------------------------------------------
__global__ __launch_bounds__(THREADS, 1)
void k_fused(const float* __restrict__ src, const float* __restrict__ trg,
             const float* __restrict__ G, float* __restrict__ out) {
    extern __shared__ unsigned char smem[];
    unsigned char* g8  = smem + SM_G8;
    float*         vec = reinterpret_cast<float*>(smem + SM_VEC);
    float*         msm = reinterpret_cast<float*>(smem + SM_MS);
    float*         ush = reinterpret_cast<float*>(smem + SM_U);
    float*         wsc = reinterpret_cast<float*>(smem + SM_W);

    const int b  = blockIdx.x;
    const int t  = threadIdx.x;
    const int r0 = b * RPC;
    const int w  = t >> 5, l = t & 31;

    // ===== P0 (warp-specialized): G-stream || mean-stream =====
    if (t < 256) {
        // --- G warps: 16 cols/thread over 32 rows -> fp8 smem + colsum0 ---
        const int c = t * 16;
        float acc[16];
#pragma unroll
        for (int k = 0; k < 16; ++k) acc[k] = 0.f;

        const float* gp0 = G + (size_t)r0 * NN + c;
        float4 n0 = ldcs4(gp0), n1 = ldcs4(gp0 + 4), n2 = ldcs4(gp0 + 8), n3 = ldcs4(gp0 + 12);
        for (int r = 0; r < RPC; ++r) {
            float4 a0 = n0, a1 = n1, a2 = n2, a3 = n3;
            if (r + 1 < RPC) {
                const float* gp = G + (size_t)(r0 + r + 1) * NN + c;
                n0 = ldcs4(gp); n1 = ldcs4(gp + 4); n2 = ldcs4(gp + 8); n3 = ldcs4(gp + 12);
            }
            float e[16] = {a0.x + EPSV, a0.y + EPSV, a0.z + EPSV, a0.w + EPSV,
                           a1.x + EPSV, a1.y + EPSV, a1.z + EPSV, a1.w + EPSV,
                           a2.x + EPSV, a2.y + EPSV, a2.z + EPSV, a2.w + EPSV,
                           a3.x + EPSV, a3.y + EPSV, a3.z + EPSV, a3.w + EPSV};
            uint4 packed;
            __nv_fp8x2_storage_t* p = reinterpret_cast<__nv_fp8x2_storage_t*>(&packed);
#pragma unroll
            for (int k = 0; k < 8; ++k) {
                p[k] = __nv_cvt_float2_to_fp8x2(make_float2(e[2 * k], e[2 * k + 1]),
                                                __NV_SATFINITE, __NV_E4M3);
                acc[2 * k]     += e[2 * k];
                acc[2 * k + 1] += e[2 * k + 1];
            }
            *reinterpret_cast<uint4*>(g8 + r * NN + c) = packed;
        }
        float* dst = d_colpart + (size_t)b * NN + c;
#pragma unroll
        for (int q = 0; q < 4; ++q)
            *reinterpret_cast<float4*>(dst + 4 * q) =
                make_float4(acc[4 * q], acc[4 * q + 1], acc[4 * q + 2], acc[4 * q + 3]);
    } else {
        // --- mean warps: 16 cols/thread over 16 rows of src AND trg ---
        const int c = (t - 256) * 16;
        const int m0 = b * MRPC;
        float accS[16], accT[16];
#pragma unroll
        for (int k = 0; k < 16; ++k) { accS[k] = 0.f; accT[k] = 0.f; }

        const float* sp0 = src + (size_t)m0 * NN + c;
        const float* tp0 = trg + (size_t)m0 * NN + c;
        float4 s0 = ldcs4(sp0), s1 = ldcs4(sp0 + 4), s2 = ldcs4(sp0 + 8), s3 = ldcs4(sp0 + 12);
        float4 t0 = ldcs4(tp0), t1 = ldcs4(tp0 + 4), t2 = ldcs4(tp0 + 8), t3 = ldcs4(tp0 + 12);
        for (int r = 0; r < MRPC; ++r) {
            float4 cs0 = s0, cs1 = s1, cs2 = s2, cs3 = s3;
            float4 ct0 = t0, ct1 = t1, ct2 = t2, ct3 = t3;
            if (r + 1 < MRPC) {
                const float* sp = src + (size_t)(m0 + r + 1) * NN + c;
                const float* tp = trg + (size_t)(m0 + r + 1) * NN + c;
                s0 = ldcs4(sp); s1 = ldcs4(sp + 4); s2 = ldcs4(sp + 8); s3 = ldcs4(sp + 12);
                t0 = ldcs4(tp); t1 = ldcs4(tp + 4); t2 = ldcs4(tp + 8); t3 = ldcs4(tp + 12);
            }
            accS[0] += cs0.x; accS[1] += cs0.y; accS[2]  += cs0.z; accS[3]  += cs0.w;
            accS[4] += cs1.x; accS[5] += cs1.y; accS[6]  += cs1.z; accS[7]  += cs1.w;
            accS[8] += cs2.x; accS[9] += cs2.y; accS[10] += cs2.z; accS[11] += cs2.w;
            accS[12]+= cs3.x; accS[13]+= cs3.y; accS[14] += cs3.z; accS[15] += cs3.w;
            accT[0] += ct0.x; accT[1] += ct0.y; accT[2]  += ct0.z; accT[3]  += ct0.w;
            accT[4] += ct1.x; accT[5] += ct1.y; accT[6]  += ct1.z; accT[7]  += ct1.w;
            accT[8] += ct2.x; accT[9] += ct2.y; accT[10] += ct2.z; accT[11] += ct2.w;
            accT[12]+= ct3.x; accT[13]+= ct3.y; accT[14] += ct3.z; accT[15] += ct3.w;
        }
        float* dS = d_meanpartS + (size_t)b * NN + c;
        float* dT = d_meanpartT + (size_t)b * NN + c;
#pragma unroll
        for (int q = 0; q < 4; ++q) {
            *reinterpret_cast<float4*>(dS + 4 * q) =
                make_float4(accS[4 * q], accS[4 * q + 1], accS[4 * q + 2], accS[4 * q + 3]);
            *reinterpret_cast<float4*>(dT + 4 * q) =
                make_float4(accT[4 * q], accT[4 * q + 1], accT[4 * q + 2], accT[4 * q + 3]);
        }
    }
    grid_barrier();

    // ===== P1: reduce colsum0 -> v1 ; reduce means =====
    {
        int col = b * 32 + (t >> 4);
        int s   = t & 15;
        float sum = 0.f, sS = 0.f, sT = 0.f;
#pragma unroll
        for (int k = 0; k < 8; ++k) {
            int cta = s * 8 + k;
            sum += __ldcg(d_colpart   + (size_t)cta * NN + col);
            sS  += __ldcg(d_meanpartS + (size_t)cta * NN + col);
            sT  += __ldcg(d_meanpartT + (size_t)cta * NN + col);
        }
#pragma unroll
        for (int off = 8; off; off >>= 1) {
            sum += __shfl_down_sync(0xffffffffu, sum, off, 16);
            sS  += __shfl_down_sync(0xffffffffu, sS,  off, 16);
            sT  += __shfl_down_sync(0xffffffffu, sT,  off, 16);
        }
        if (s == 0) {
            d_v[col]        = 1.0f / sum;
            d_mean_src[col] = sS * (1.0f / (float)BB);
            d_mean_trg[col] = sT * (1.0f / (float)BB);
        }
    }
    grid_barrier();

    // ===== P2: u1 per row + colsum(u1) partials (pure SMEM) =====
    {
        const int c = t * 8;
        *reinterpret_cast<float4*>(vec + c)     = __ldcg(reinterpret_cast<const float4*>(d_v + c));
        *reinterpret_cast<float4*>(vec + c + 4) = __ldcg(reinterpret_cast<const float4*>(d_v + c + 4));
        __syncthreads();

#pragma unroll
        for (int rr = 0; rr < 2; ++rr) {
            int r = w + rr * 16;
            const unsigned char* grow = g8 + r * NN;
            float a = 0.f;
#pragma unroll 8
            for (int k = 0; k < 32; ++k) {
                int j = l * 4 + k * 128;
                unsigned raw = *reinterpret_cast<const unsigned*>(grow + j);
                float f[4];
                fp8x4_to_f32(raw, f);
                float4 vv = *reinterpret_cast<const float4*>(vec + j);
                a += f[0] * vv.x + f[1] * vv.y + f[2] * vv.z + f[3] * vv.w;
            }
#pragma unroll
            for (int off = 16; off; off >>= 1) a += __shfl_down_sync(0xffffffffu, a, off);
            if (l == 0) ush[r] = 1.0f / a;
        }
        __syncthreads();

        float acc[8] = {0.f, 0.f, 0.f, 0.f, 0.f, 0.f, 0.f, 0.f};
        for (int r = 0; r < RPC; ++r) {
            float u = ush[r];
            uint2 raw = *reinterpret_cast<const uint2*>(g8 + r * NN + c);
            float f[8];
            fp8x4_to_f32(raw.x, f);
            fp8x4_to_f32(raw.y, f + 4);
#pragma unroll
            for (int k = 0; k < 8; ++k) acc[k] += u * f[k];
        }
        float* dst = d_colpart + (size_t)b * NN + c;
        *reinterpret_cast<float4*>(dst)     = make_float4(acc[0], acc[1], acc[2], acc[3]);
        *reinterpret_cast<float4*>(dst + 4) = make_float4(acc[4], acc[5], acc[6], acc[7]);
    }
    grid_barrier();

    // ===== P3: reduce -> v2 =====
    {
        int col = b * 32 + (t >> 4);
        int s   = t & 15;
        float sum = 0.f;
#pragma unroll
        for (int k = 0; k < 8; ++k)
            sum += __ldcg(d_colpart + (size_t)(s * 8 + k) * NN + col);
#pragma unroll
        for (int off = 8; off; off >>= 1) sum += __shfl_down_sync(0xffffffffu, sum, off, 16);
        if (s == 0) d_v[col] = 1.0f / sum;
    }
    grid_barrier();

    // ===== P4: exact row-normalize + loss; CTA partial =====
    {
        const int c = t * 8;
        *reinterpret_cast<float4*>(vec + c)     = __ldcg(reinterpret_cast<const float4*>(d_v + c));
        *reinterpret_cast<float4*>(vec + c + 4) = __ldcg(reinterpret_cast<const float4*>(d_v + c + 4));
        *reinterpret_cast<float4*>(msm + c)     = __ldcg(reinterpret_cast<const float4*>(d_mean_src + c));
        *reinterpret_cast<float4*>(msm + c + 4) = __ldcg(reinterpret_cast<const float4*>(d_mean_src + c + 4));
        __syncthreads();

        float part = 0.f;
#pragma unroll
        for (int rr = 0; rr < 2; ++rr) {
            int r = w + rr * 16;
            float mt = __ldcg(d_mean_trg + r0 + r);
            const unsigned char* grow = g8 + r * NN;
            float at = 0.f, aw = 0.f;
#pragma unroll 8
            for (int k = 0; k < 32; ++k) {
                int j = l * 4 + k * 128;
                unsigned raw = *reinterpret_cast<const unsigned*>(grow + j);
                float f[4];
                fp8x4_to_f32(raw, f);
                float4 vv = *reinterpret_cast<const float4*>(vec + j);
                float4 mm = *reinterpret_cast<const float4*>(msm + j);
                float gv0 = f[0] * vv.x, gv1 = f[1] * vv.y;
                float gv2 = f[2] * vv.z, gv3 = f[3] * vv.w;
                at += gv0 + gv1 + gv2 + gv3;
                aw += fabsf(mt - mm.x) * gv0 + fabsf(mt - mm.y) * gv1
                    + fabsf(mt - mm.z) * gv2 + fabsf(mt - mm.w) * gv3;
            }
#pragma unroll
            for (int off = 16; off; off >>= 1) {
                at += __shfl_down_sync(0xffffffffu, at, off);
                aw += __shfl_down_sync(0xffffffffu, aw, off);
            }
            if (l == 0) part += aw / at;
        }
        if (l == 0) wsc[w] = part;
        __syncthreads();
        if (t == 0) {
            float s = 0.f;
#pragma unroll
            for (int k = 0; k < 16; ++k) s += wsc[k];
            d_ctapart[b] = s;
        }
    }
    grid_barrier();

    // ===== P5: CTA 0 reduces 128 partials =====
    if (b == 0 && t < 32) {
        float s = 0.f;
#pragma unroll
        for (int k = 0; k < NCTA / 32; ++k) s += __ldcg(d_ctapart + t + 32 * k);
#pragma unroll
        for (int off = 16; off; off >>= 1) s += __shfl_down_sync(0xffffffffu, s, off);
        if (t == 0) out[0] = s;
    }
}

// ---------------------------------------------------------------------------
extern "C" void kernel_launch(void* const* d_in, const int* in_sizes, int n_in,
                              void* d_out, int out_size) {
    (void)in_sizes; (void)n_in; (void)out_size;
    const float* src = (const float*)d_in[0];
    const float* trg = (const float*)d_in[1];
    const float* G   = (const float*)d_in[2];
    float* out = (float*)d_out;

    cudaFuncSetAttribute(k_fused, cudaFuncAttributeMaxDynamicSharedMemorySize, SM_TOT);
    k_fused<<<NCTA, THREADS, SM_TOT>>>(src, trg, G, out);
}

// round 10
// speedup vs baseline: 1.0439x; 1.0427x over previous
#include <cuda_runtime.h>
#include <cuda_fp16.h>
#include <cuda_fp8.h>

// Inter_domain_loss as ONE persistent kernel, v4: cp.async pipelined G stream.
// 128 CTAs x 512 threads. Warps 0-7: G rows via cp.async.cg into a 4-deep fp32
// smem staging ring (64 KB async in flight, no register gating), convert to
// fp8 smem + colsum0. Warps 8-15: concurrent deep-LDG mean stream.
// Staging aliases vec/msm (dead until P2). 2 Sinkhorn iterations (fp8,
// rel_err ~2.5e-6 validated R6-R9).

#define NN      4096
#define BB      2048
#define EPSV    1e-5f
#define NCTA    128
#define RPC     32            // G rows per CTA
#define MRPC    16            // src/trg rows per CTA
#define THREADS 512
#define SDEPTH  4             // staging ring depth (rows)

// smem layout (dynamic). Staging (64 KB) aliases vec (16 KB) + msm (16 KB).
#define SM_G8    0                           // 32*4096 fp8 = 131072
#define SM_STAGE 131072                      // 4*4096 fp32 = 65536
#define SM_VEC   131072                      // alias (P2+)
#define SM_MS    (131072 + 16384)            // alias (P4)
#define SM_U     (131072 + 65536)            // 32 floats = 128
#define SM_W     (131072 + 65536 + 128)      // 16 floats = 64
#define SM_TOT   (131072 + 65536 + 128 + 64)

// Global scratch
__device__ float d_colpart[NCTA * NN];
__device__ float d_meanpartS[NCTA * NN];
__device__ float d_meanpartT[NCTA * NN];
__device__ float d_v[NN];
__device__ float d_mean_src[NN];
__device__ float d_mean_trg[NN];
__device__ float d_ctapart[NCTA];
__device__ unsigned d_barcnt = 0;
__device__ unsigned d_bargen = 0;

#define CP_ASYNC16(dst, src) \
    asm volatile("cp.async.cg.shared.global [%0], [%1], 16;\n" \
                 :: "r"(dst), "l"(src))
#define CP_COMMIT() asm volatile("cp.async.commit_group;\n" ::: "memory")
#define CP_WAIT3()  asm volatile("cp.async.wait_group 3;\n" ::: "memory")
#define CP_WAIT0()  asm volatile("cp.async.wait_group 0;\n" ::: "memory")

// ---------------------------------------------------------------------------
__device__ __forceinline__ void grid_barrier() {
    __syncthreads();
    if (threadIdx.x == 0) {
        __threadfence();
        unsigned gen = atomicAdd(&d_bargen, 0u);
        unsigned old = atomicAdd(&d_barcnt, 1u);
        if (old == NCTA - 1) {
            atomicExch(&d_barcnt, 0u);
            atomicAdd(&d_bargen, 1u);
        } else {
            while (atomicAdd(&d_bargen, 0u) == gen) __nanosleep(32);
        }
    }
    __syncthreads();
}

__device__ __forceinline__ void fp8x4_to_f32(unsigned raw, float* f) {
    __half2_raw h0 = __nv_cvt_fp8x2_to_halfraw2((__nv_fp8x2_storage_t)(raw & 0xFFFFu), __NV_E4M3);
    __half2_raw h1 = __nv_cvt_fp8x2_to_halfraw2((__nv_fp8x2_storage_t)(raw >> 16), __NV_E4M3);
    float2 a = __half22float2(*reinterpret_cast<__half2*>(&h0));
    float2 b = __half22float2(*reinterpret_cast<__half2*>(&h1));
    f[0] = a.x; f[1] = a.y; f[2] = b.x; f[3] = b.y;
}

__device__ __forceinline__ float4 ldcs4(const float* p) {
    return __ldcs(reinterpret_cast<const float4*>(p));
}

// ---------------------------------------------------------------------------
__global__ __launch_bounds__(THREADS, 1)
void k_fused(const float* __restrict__ src, const float* __restrict__ trg,
             const float* __restrict__ G, float* __restrict__ out) {
    extern __shared__ unsigned char smem[];
    unsigned char* g8  = smem + SM_G8;
    float*         vec = reinterpret_cast<float*>(smem + SM_VEC);
    float*         msm = reinterpret_cast<float*>(smem + SM_MS);
    float*         ush = reinterpret_cast<float*>(smem + SM_U);
    float*         wsc = reinterpret_cast<float*>(smem + SM_W);

    const int b  = blockIdx.x;
    const int t  = threadIdx.x;
    const int r0 = b * RPC;
    const int w  = t >> 5, l = t & 31;

    unsigned stage_base;
    {
        const void* sp = smem + SM_STAGE;
        asm("{ .reg .u64 tmp; cvta.to.shared.u64 tmp, %1; cvt.u32.u64 %0, tmp; }"
            : "=r"(stage_base) : "l"(sp));
    }

    // ===== P0 (warp-specialized): cp.async G pipeline || deep-LDG means =====
    if (t < 256) {
        // --- G warps: thread owns 16 cols (4 float4) of each row ---
        const int c = t * 16;
        float acc[16];
#pragma unroll
        for (int k = 0; k < 16; ++k) acc[k] = 0.f;

        // prologue: rows 0..2 in flight (3 groups)
#pragma unroll
        for (int d = 0; d < SDEPTH - 1; ++d) {
            const float* gp = G + (size_t)(r0 + d) * NN + c;
            unsigned sdst = stage_base + (unsigned)((d * NN + c) * 4);
#pragma unroll
            for (int q = 0; q < 4; ++q) CP_ASYNC16(sdst + 16u * q, gp + 4 * q);
            CP_COMMIT();
        }

        for (int r = 0; r < RPC; ++r) {
            if (r + SDEPTH - 1 < RPC) {
                const float* gp = G + (size_t)(r0 + r + SDEPTH - 1) * NN + c;
                unsigned sdst = stage_base + (unsigned)((((r + SDEPTH - 1) & (SDEPTH - 1)) * NN + c) * 4);
#pragma unroll
                for (int q = 0; q < 4; ++q) CP_ASYNC16(sdst + 16u * q, gp + 4 * q);
            }
            CP_COMMIT();          // empty group when no issue — keeps count aligned
            CP_WAIT3();           // row r resident

            const float* st = reinterpret_cast<const float*>(smem + SM_STAGE)
                              + (r & (SDEPTH - 1)) * NN + c;
            float4 a0 = *reinterpret_cast<const float4*>(st);
            float4 a1 = *reinterpret_cast<const float4*>(st + 4);
            float4 a2 = *reinterpret_cast<const float4*>(st + 8);
            float4 a3 = *reinterpret_cast<const float4*>(st + 12);
            float e[16] = {a0.x + EPSV, a0.y + EPSV, a0.z + EPSV, a0.w + EPSV,
                           a1.x + EPSV, a1.y + EPSV, a1.z + EPSV, a1.w + EPSV,
                           a2.x + EPSV, a2.y + EPSV, a2.z + EPSV, a2.w + EPSV,
                           a3.x + EPSV, a3.y + EPSV, a3.z + EPSV, a3.w + EPSV};
            uint4 packed;
            __nv_fp8x2_storage_t* p = reinterpret_cast<__nv_fp8x2_storage_t*>(&packed);
#pragma unroll
            for (int k = 0; k < 8; ++k) {
                p[k] = __nv_cvt_float2_to_fp8x2(make_float2(e[2 * k], e[2 * k + 1]),
                                                __NV_SATFINITE, __NV_E4M3);
                acc[2 * k]     += e[2 * k];
                acc[2 * k + 1] += e[2 * k + 1];
            }
            *reinterpret_cast<uint4*>(g8 + r * NN + c) = packed;
        }
        CP_WAIT0();

        float* dst = d_colpart + (size_t)b * NN + c;
#pragma unroll
        for (int q = 0; q < 4; ++q)
            *reinterpret_cast<float4*>(dst + 4 * q) =
                make_float4(acc[4 * q], acc[4 * q + 1], acc[4 * q + 2], acc[4 * q + 3]);
    } else {
        // --- mean warps: 16 cols/thread over 16 rows of src AND trg ---
        const int c = (t - 256) * 16;
        const int m0 = b * MRPC;
        float accS[16], accT[16];
#pragma unroll
        for (int k = 0; k < 16; ++k) { accS[k] = 0.f; accT[k] = 0.f; }

        const float* sp0 = src + (size_t)m0 * NN + c;
        const float* tp0 = trg + (size_t)m0 * NN + c;
        float4 s0 = ldcs4(sp0), s1 = ldcs4(sp0 + 4), s2 = ldcs4(sp0 + 8), s3 = ldcs4(sp0 + 12);
        float4 t0 = ldcs4(tp0), t1 = ldcs4(tp0 + 4), t2 = ldcs4(tp0 + 8), t3 = ldcs4(tp0 + 12);
        for (int r = 0; r < MRPC; ++r) {
            float4 cs0 = s0, cs1 = s1, cs2 = s2, cs3 = s3;
            float4 ct0 = t0, ct1 = t1, ct2 = t2, ct3 = t3;
            if (r + 1 < MRPC) {
                const float* sp = src + (size_t)(m0 + r + 1) * NN + c;
                const float* tp = trg + (size_t)(m0 + r + 1) * NN + c;
                s0 = ldcs4(sp); s1 = ldcs4(sp + 4); s2 = ldcs4(sp + 8); s3 = ldcs4(sp + 12);
                t0 = ldcs4(tp); t1 = ldcs4(tp + 4); t2 = ldcs4(tp + 8); t3 = ldcs4(tp + 12);
            }
            accS[0] += cs0.x; accS[1] += cs0.y; accS[2]  += cs0.z; accS[3]  += cs0.w;
            accS[4] += cs1.x; accS[5] += cs1.y; accS[6]  += cs1.z; accS[7]  += cs1.w;
            accS[8] += cs2.x; accS[9] += cs2.y; accS[10] += cs2.z; accS[11] += cs2.w;
            accS[12]+= cs3.x; accS[13]+= cs3.y; accS[14] += cs3.z; accS[15] += cs3.w;
            accT[0] += ct0.x; accT[1] += ct0.y; accT[2]  += ct0.z; accT[3]  += ct0.w;
            accT[4] += ct1.x; accT[5] += ct1.y; accT[6]  += ct1.z; accT[7]  += ct1.w;
            accT[8] += ct2.x; accT[9] += ct2.y; accT[10] += ct2.z; accT[11] += ct2.w;
            accT[12]+= ct3.x; accT[13]+= ct3.y; accT[14] += ct3.z; accT[15] += ct3.w;
        }
        float* dS = d_meanpartS + (size_t)b * NN + c;
        float* dT = d_meanpartT + (size_t)b * NN + c;
#pragma unroll
        for (int q = 0; q < 4; ++q) {
            *reinterpret_cast<float4*>(dS + 4 * q) =
                make_float4(accS[4 * q], accS[4 * q + 1], accS[4 * q + 2], accS[4 * q + 3]);
            *reinterpret_cast<float4*>(dT + 4 * q) =
                make_float4(accT[4 * q], accT[4 * q + 1], accT[4 * q + 2], accT[4 * q + 3]);
        }
    }
    grid_barrier();

    // ===== P1: reduce colsum0 -> v1 ; reduce means =====
    {
        int col = b * 32 + (t >> 4);
        int s   = t & 15;
        float sum = 0.f, sS = 0.f, sT = 0.f;
#pragma unroll
        for (int k = 0; k < 8; ++k) {
            int cta = s * 8 + k;
            sum += __ldcg(d_colpart   + (size_t)cta * NN + col);
            sS  += __ldcg(d_meanpartS + (size_t)cta * NN + col);
            sT  += __ldcg(d_meanpartT + (size_t)cta * NN + col);
        }
#pragma unroll
        for (int off = 8; off; off >>= 1) {
            sum += __shfl_down_sync(0xffffffffu, sum, off, 16);
            sS  += __shfl_down_sync(0xffffffffu, sS,  off, 16);
            sT  += __shfl_down_sync(0xffffffffu, sT,  off, 16);
        }
        if (s == 0) {
            d_v[col]        = 1.0f / sum;
            d_mean_src[col] = sS * (1.0f / (float)BB);
            d_mean_trg[col] = sT * (1.0f / (float)BB);
        }
    }
    grid_barrier();

    // ===== P2: u1 per row + colsum(u1) partials (pure SMEM) =====
    {
        const int c = t * 8;
        *reinterpret_cast<float4*>(vec + c)     = __ldcg(reinterpret_cast<const float4*>(d_v + c));
        *reinterpret_cast<float4*>(vec + c + 4) = __ldcg(reinterpret_cast<const float4*>(d_v + c + 4));
        __syncthreads();

#pragma unroll
        for (int rr = 0; rr < 2; ++rr) {
            int r = w + rr * 16;
            const unsigned char* grow = g8 + r * NN;
            float a = 0.f;
#pragma unroll 8
            for (int k = 0; k < 32; ++k) {
                int j = l * 4 + k * 128;
                unsigned raw = *reinterpret_cast<const unsigned*>(grow + j);
                float f[4];
                fp8x4_to_f32(raw, f);
                float4 vv = *reinterpret_cast<const float4*>(vec + j);
                a += f[0] * vv.x + f[1] * vv.y + f[2] * vv.z + f[3] * vv.w;
            }
#pragma unroll
            for (int off = 16; off; off >>= 1) a += __shfl_down_sync(0xffffffffu, a, off);
            if (l == 0) ush[r] = 1.0f / a;
        }
        __syncthreads();

        float acc[8] = {0.f, 0.f, 0.f, 0.f, 0.f, 0.f, 0.f, 0.f};
        for (int r = 0; r < RPC; ++r) {
            float u = ush[r];
            uint2 raw = *reinterpret_cast<const uint2*>(g8 + r * NN + c);
            float f[8];
            fp8x4_to_f32(raw.x, f);
            fp8x4_to_f32(raw.y, f + 4);
#pragma unroll
            for (int k = 0; k < 8; ++k) acc[k] += u * f[k];
        }
        float* dst = d_colpart + (size_t)b * NN + c;
        *reinterpret_cast<float4*>(dst)     = make_float4(acc[0], acc[1], acc[2], acc[3]);
        *reinterpret_cast<float4*>(dst + 4) = make_float4(acc[4], acc[5], acc[6], acc[7]);
    }
    grid_barrier();

    // ===== P3: reduce -> v2 =====
    {
        int col = b * 32 + (t >> 4);
        int s   = t & 15;
        float sum = 0.f;
#pragma unroll
        for (int k = 0; k < 8; ++k)
            sum += __ldcg(d_colpart + (size_t)(s * 8 + k) * NN + col);
#pragma unroll
        for (int off = 8; off; off >>= 1) sum += __shfl_down_sync(0xffffffffu, sum, off, 16);
        if (s == 0) d_v[col] = 1.0f / sum;
    }
    grid_barrier();

    // ===== P4: exact row-normalize + loss; CTA partial =====
    {
        const int c = t * 8;
        *reinterpret_cast<float4*>(vec + c)     = __ldcg(reinterpret_cast<const float4*>(d_v + c));
        *reinterpret_cast<float4*>(vec + c + 4) = __ldcg(reinterpret_cast<const float4*>(d_v + c + 4));
        *reinterpret_cast<float4*>(msm + c)     = __ldcg(reinterpret_cast<const float4*>(d_mean_src + c));
        *reinterpret_cast<float4*>(msm + c + 4) = __ldcg(reinterpret_cast<const float4*>(d_mean_src + c + 4));
        __syncthreads();

        float part = 0.f;
#pragma unroll
        for (int rr = 0; rr < 2; ++rr) {
            int r = w + rr * 16;
            float mt = __ldcg(d_mean_trg + r0 + r);
            const unsigned char* grow = g8 + r * NN;
            float at = 0.f, aw = 0.f;
#pragma unroll 8
            for (int k = 0; k < 32; ++k) {
                int j = l * 4 + k * 128;
                unsigned raw = *reinterpret_cast<const unsigned*>(grow + j);
                float f[4];
                fp8x4_to_f32(raw, f);
                float4 vv = *reinterpret_cast<const float4*>(vec + j);
                float4 mm = *reinterpret_cast<const float4*>(msm + j);
                float gv0 = f[0] * vv.x, gv1 = f[1] * vv.y;
                float gv2 = f[2] * vv.z, gv3 = f[3] * vv.w;
                at += gv0 + gv1 + gv2 + gv3;
                aw += fabsf(mt - mm.x) * gv0 + fabsf(mt - mm.y) * gv1
                    + fabsf(mt - mm.z) * gv2 + fabsf(mt - mm.w) * gv3;
            }
#pragma unroll
            for (int off = 16; off; off >>= 1) {
                at += __shfl_down_sync(0xffffffffu, at, off);
                aw += __shfl_down_sync(0xffffffffu, aw, off);
            }
            if (l == 0) part += aw / at;
        }
        if (l == 0) wsc[w] = part;
        __syncthreads();
        if (t == 0) {
            float s = 0.f;
#pragma unroll
            for (int k = 0; k < 16; ++k) s += wsc[k];
            d_ctapart[b] = s;
        }
    }
    grid_barrier();

    // ===== P5: CTA 0 reduces 128 partials =====
    if (b == 0 && t < 32) {
        float s = 0.f;
#pragma unroll
        for (int k = 0; k < NCTA / 32; ++k) s += __ldcg(d_ctapart + t + 32 * k);
#pragma unroll
        for (int off = 16; off; off >>= 1) s += __shfl_down_sync(0xffffffffu, s, off);
        if (t == 0) out[0] = s;
    }
}

// ---------------------------------------------------------------------------
extern "C" void kernel_launch(void* const* d_in, const int* in_sizes, int n_in,
                              void* d_out, int out_size) {
    (void)in_sizes; (void)n_in; (void)out_size;
    const float* src = (const float*)d_in[0];
    const float* trg = (const float*)d_in[1];
    const float* G   = (const float*)d_in[2];
    float* out = (float*)d_out;

    cudaFuncSetAttribute(k_fused, cudaFuncAttributeMaxDynamicSharedMemorySize, SM_TOT);
    k_fused<<<NCTA, THREADS, SM_TOT>>>(src, trg, G, out);
}

// round 11
// speedup vs baseline: 1.0756x; 1.0304x over previous
#include <cuda_runtime.h>
#include <cuda_fp16.h>
#include <cuda_fp8.h>

// Inter_domain_loss as ONE persistent kernel, v5: register-resident vectors +
// butterfly array-reductions kill the smem vector re-reads of v4.
// 128 CTAs x 512 threads; CTA holds 32 rows fp8(G+eps) in SMEM.
// P0: cp.async G pipeline (warps 0-7) || deep-LDG mean stream (warps 8-15).
// 2 Sinkhorn iterations (fp8, rel_err ~2.5e-6 validated R6-R10).

#define NN      4096
#define BB      2048
#define EPSV    1e-5f
#define NCTA    128
#define RPC     32
#define MRPC    16
#define THREADS 512
#define SDEPTH  4

// smem layout
#define SM_G8    0                    // 131072
#define SM_STAGE 131072               // 65536 (P0 staging ring)
#define SM_RED   196608               // 2048: wpart[16*32] / redT+redW
#define SM_U     198656               // 128: ush[32]
#define SM_MT    198784               // 128: mtr[32]
#define SM_TOT   198912

// Global scratch
__device__ float d_colpart[NCTA * NN];
__device__ float d_meanpartS[NCTA * NN];
__device__ float d_meanpartT[NCTA * NN];
__device__ float d_v[NN];
__device__ float d_mean_src[NN];
__device__ float d_mean_trg[NN];
__device__ float d_ctapart[NCTA];
__device__ unsigned d_barcnt = 0;
__device__ unsigned d_bargen = 0;

#define CP_ASYNC16(dst, src) \
    asm volatile("cp.async.cg.shared.global [%0], [%1], 16;\n" :: "r"(dst), "l"(src))
#define CP_COMMIT() asm volatile("cp.async.commit_group;\n" ::: "memory")
#define CP_WAIT3()  asm volatile("cp.async.wait_group 3;\n" ::: "memory")
#define CP_WAIT0()  asm volatile("cp.async.wait_group 0;\n" ::: "memory")

// ---------------------------------------------------------------------------
__device__ __forceinline__ void grid_barrier() {
    __syncthreads();
    if (threadIdx.x == 0) {
        __threadfence();
        unsigned gen = atomicAdd(&d_bargen, 0u);
        unsigned old = atomicAdd(&d_barcnt, 1u);
        if (old == NCTA - 1) {
            atomicExch(&d_barcnt, 0u);
            atomicAdd(&d_bargen, 1u);
        } else {
            while (atomicAdd(&d_bargen, 0u) == gen) __nanosleep(32);
        }
    }
    __syncthreads();
}

__device__ __forceinline__ void fp8x4_to_f32(unsigned raw, float* f) {
    __half2_raw h0 = __nv_cvt_fp8x2_to_halfraw2((__nv_fp8x2_storage_t)(raw & 0xFFFFu), __NV_E4M3);
    __half2_raw h1 = __nv_cvt_fp8x2_to_halfraw2((__nv_fp8x2_storage_t)(raw >> 16), __NV_E4M3);
    float2 a = __half22float2(*reinterpret_cast<__half2*>(&h0));
    float2 b = __half22float2(*reinterpret_cast<__half2*>(&h1));
    f[0] = a.x; f[1] = a.y; f[2] = b.x; f[3] = b.y;
}

__device__ __forceinline__ float4 ldcs4(const float* p) {
    return __ldcs(reinterpret_cast<const float4*>(p));
}

// Butterfly array-reduce: 32 per-lane values -> lane l returns total of row l.
__device__ __forceinline__ float bfly_reduce32(const float* a, int l) {
    float b[16];
#pragma unroll
    for (int r = 0; r < 16; ++r) {
        bool hi = (l & 16);
        float send = hi ? a[r] : a[r + 16];
        float keep = hi ? a[r + 16] : a[r];
        b[r] = keep + __shfl_xor_sync(0xffffffffu, send, 16);
    }
    float c[8];
#pragma unroll
    for (int r = 0; r < 8; ++r) {
        bool hi = (l & 8);
        float send = hi ? b[r] : b[r + 8];
        float keep = hi ? b[r + 8] : b[r];
        c[r] = keep + __shfl_xor_sync(0xffffffffu, send, 8);
    }
    float d[4];
#pragma unroll
    for (int r = 0; r < 4; ++r) {
        bool hi = (l & 4);
        float send = hi ? c[r] : c[r + 4];
        float keep = hi ? c[r + 4] : c[r];
        d[r] = keep + __shfl_xor_sync(0xffffffffu, send, 4);
    }
    float e[2];
#pragma unroll
    for (int r = 0; r < 2; ++r) {
        bool hi = (l & 2);
        float send = hi ? d[r] : d[r + 2];
        float keep = hi ? d[r + 2] : d[r];
        e[r] = keep + __shfl_xor_sync(0xffffffffu, send, 2);
    }
    bool hi = (l & 1);
    float send = hi ? e[0] : e[1];
    float keep = hi ? e[1] : e[0];
    return keep + __shfl_xor_sync(0xffffffffu, send, 1);
}

// 16 per-lane values -> lanes l and l+16 return total of row (l & 15).
__device__ __forceinline__ float bfly_reduce16(const float* a, int l) {
    float b[16];
#pragma unroll
    for (int r = 0; r < 16; ++r) b[r] = a[r] + __shfl_xor_sync(0xffffffffu, a[r], 16);
    float c[8];
#pragma unroll
    for (int r = 0; r < 8; ++r) {
        bool hi = (l & 8);
        float send = hi ? b[r] : b[r + 8];
        float keep = hi ? b[r + 8] : b[r];
        c[r] = keep + __shfl_xor_sync(0xffffffffu, send, 8);
    }
    float d[4];
#pragma unroll
    for (int r = 0; r < 4; ++r) {
        bool hi = (l & 4);
        float send = hi ? c[r] : c[r + 4];
        float keep = hi ? c[r + 4] : c[r];
        d[r] = keep + __shfl_xor_sync(0xffffffffu, send, 4);
    }
    float e[2];
#pragma unroll
    for (int r = 0; r < 2; ++r) {
        bool hi = (l & 2);
        float send = hi ? d[r] : d[r + 2];
        float keep = hi ? d[r + 2] : d[r];
        e[r] = keep + __shfl_xor_sync(0xffffffffu, send, 2);
    }
    bool hi = (l & 1);
    float send = hi ? e[0] : e[1];
    float keep = hi ? e[1] : e[0];
    return keep + __shfl_xor_sync(0xffffffffu, send, 1);
}

// ---------------------------------------------------------------------------
__global__ __launch_bounds__(THREADS, 1)
void k_fused(const float* __restrict__ src, const float* __restrict__ trg,
             const float* __restrict__ G, float* __restrict__ out) {
    extern __shared__ unsigned char smem[];
    unsigned char* g8  = smem + SM_G8;
    float* wpart = reinterpret_cast<float*>(smem + SM_RED);        // [16][32]
    float* redT  = reinterpret_cast<float*>(smem + SM_RED);        // [16][16]
    float* redW  = reinterpret_cast<float*>(smem + SM_RED + 1024); // [16][16]
    float* ush   = reinterpret_cast<float*>(smem + SM_U);
    float* mtr   = reinterpret_cast<float*>(smem + SM_MT);

    const int b  = blockIdx.x;
    const int t  = threadIdx.x;
    const int r0 = b * RPC;
    const int w  = t >> 5, l = t & 31;

    unsigned stage_base;
    {
        const void* sp = smem + SM_STAGE;
        asm("{ .reg .u64 tmp; cvta.to.shared.u64 tmp, %1; cvt.u32.u64 %0, tmp; }"
            : "=r"(stage_base) : "l"(sp));
    }

    // ===== P0 (warp-specialized): cp.async G pipeline || deep-LDG means =====
    if (t < 256) {
        const int c = t * 16;
        float acc[16];
#pragma unroll
        for (int k = 0; k < 16; ++k) acc[k] = 0.f;

#pragma unroll
        for (int d = 0; d < SDEPTH - 1; ++d) {
            const float* gp = G + (size_t)(r0 + d) * NN + c;
            unsigned sdst = stage_base + (unsigned)((d * NN + c) * 4);
#pragma unroll
            for (int q = 0; q < 4; ++q) CP_ASYNC16(sdst + 16u * q, gp + 4 * q);
            CP_COMMIT();
        }

        for (int r = 0; r < RPC; ++r) {
            if (r + SDEPTH - 1 < RPC) {
                const float* gp = G + (size_t)(r0 + r + SDEPTH - 1) * NN + c;
                unsigned sdst = stage_base + (unsigned)((((r + SDEPTH - 1) & (SDEPTH - 1)) * NN + c) * 4);
#pragma unroll
                for (int q = 0; q < 4; ++q) CP_ASYNC16(sdst + 16u * q, gp + 4 * q);
            }
            CP_COMMIT();
            CP_WAIT3();

            const float* st = reinterpret_cast<const float*>(smem + SM_STAGE)
                              + (r & (SDEPTH - 1)) * NN + c;
            float4 a0 = *reinterpret_cast<const float4*>(st);
            float4 a1 = *reinterpret_cast<const float4*>(st + 4);
            float4 a2 = *reinterpret_cast<const float4*>(st + 8);
            float4 a3 = *reinterpret_cast<const float4*>(st + 12);
            float e[16] = {a0.x + EPSV, a0.y + EPSV, a0.z + EPSV, a0.w + EPSV,
                           a1.x + EPSV, a1.y + EPSV, a1.z + EPSV, a1.w + EPSV,
                           a2.x + EPSV, a2.y + EPSV, a2.z + EPSV, a2.w + EPSV,
                           a3.x + EPSV, a3.y + EPSV, a3.z + EPSV, a3.w + EPSV};
            uint4 packed;
            __nv_fp8x2_storage_t* p = reinterpret_cast<__nv_fp8x2_storage_t*>(&packed);
#pragma unroll
            for (int k = 0; k < 8; ++k) {
                p[k] = __nv_cvt_float2_to_fp8x2(make_float2(e[2 * k], e[2 * k + 1]),
                                                __NV_SATFINITE, __NV_E4M3);
                acc[2 * k]     += e[2 * k];
                acc[2 * k + 1] += e[2 * k + 1];
            }
            *reinterpret_cast<uint4*>(g8 + r * NN + c) = packed;
        }
        CP_WAIT0();

        float* dst = d_colpart + (size_t)b * NN + c;
#pragma unroll
        for (int q = 0; q < 4; ++q)
            *reinterpret_cast<float4*>(dst + 4 * q) =
                make_float4(acc[4 * q], acc[4 * q + 1], acc[4 * q + 2], acc[4 * q + 3]);
    } else {
        const int c = (t - 256) * 16;
        const int m0 = b * MRPC;
        float accS[16], accT[16];
#pragma unroll
        for (int k = 0; k < 16; ++k) { accS[k] = 0.f; accT[k] = 0.f; }

        const float* sp0 = src + (size_t)m0 * NN + c;
        const float* tp0 = trg + (size_t)m0 * NN + c;
        float4 s0 = ldcs4(sp0), s1 = ldcs4(sp0 + 4), s2 = ldcs4(sp0 + 8), s3 = ldcs4(sp0 + 12);
        float4 t0 = ldcs4(tp0), t1 = ldcs4(tp0 + 4), t2 = ldcs4(tp0 + 8), t3 = ldcs4(tp0 + 12);
        for (int r = 0; r < MRPC; ++r) {
            float4 cs0 = s0, cs1 = s1, cs2 = s2, cs3 = s3;
            float4 ct0 = t0, ct1 = t1, ct2 = t2, ct3 = t3;
            if (r + 1 < MRPC) {
                const float* sp = src + (size_t)(m0 + r + 1) * NN + c;
                const float* tp = trg + (size_t)(m0 + r + 1) * NN + c;
                s0 = ldcs4(sp); s1 = ldcs4(sp + 4); s2 = ldcs4(sp + 8); s3 = ldcs4(sp + 12);
                t0 = ldcs4(tp); t1 = ldcs4(tp + 4); t2 = ldcs4(tp + 8); t3 = ldcs4(tp + 12);
            }
            accS[0] += cs0.x; accS[1] += cs0.y; accS[2]  += cs0.z; accS[3]  += cs0.w;
            accS[4] += cs1.x; accS[5] += cs1.y; accS[6]  += cs1.z; accS[7]  += cs1.w;
            accS[8] += cs2.x; accS[9] += cs2.y; accS[10] += cs2.z; accS[11] += cs2.w;
            accS[12]+= cs3.x; accS[13]+= cs3.y; accS[14] += cs3.z; accS[15] += cs3.w;
            accT[0] += ct0.x; accT[1] += ct0.y; accT[2]  += ct0.z; accT[3]  += ct0.w;
            accT[4] += ct1.x; accT[5] += ct1.y; accT[6]  += ct1.z; accT[7]  += ct1.w;
            accT[8] += ct2.x; accT[9] += ct2.y; accT[10] += ct2.z; accT[11] += ct2.w;
            accT[12]+= ct3.x; accT[13]+= ct3.y; accT[14] += ct3.z; accT[15] += ct3.w;
        }
        float* dS = d_meanpartS + (size_t)b * NN + c;
        float* dT = d_meanpartT + (size_t)b * NN + c;
#pragma unroll
        for (int q = 0; q < 4; ++q) {
            *reinterpret_cast<float4*>(dS + 4 * q) =
                make_float4(accS[4 * q], accS[4 * q + 1], accS[4 * q + 2], accS[4 * q + 3]);
            *reinterpret_cast<float4*>(dT + 4 * q) =
                make_float4(accT[4 * q], accT[4 * q + 1], accT[4 * q + 2], accT[4 * q + 3]);
        }
    }
    grid_barrier();

    // ===== P1: reduce colsum0 -> v1 ; reduce means =====
    {
        int col = b * 32 + (t >> 4);
        int s   = t & 15;
        float sum = 0.f, sS = 0.f, sT = 0.f;
#pragma unroll
        for (int k = 0; k < 8; ++k) {
            int cta = s * 8 + k;
            sum += __ldcg(d_colpart   + (size_t)cta * NN + col);
            sS  += __ldcg(d_meanpartS + (size_t)cta * NN + col);
            sT  += __ldcg(d_meanpartT + (size_t)cta * NN + col);
        }
#pragma unroll
        for (int off = 8; off; off >>= 1) {
            sum += __shfl_down_sync(0xffffffffu, sum, off, 16);
            sS  += __shfl_down_sync(0xffffffffu, sS,  off, 16);
            sT  += __shfl_down_sync(0xffffffffu, sT,  off, 16);
        }
        if (s == 0) {
            d_v[col]        = 1.0f / sum;
            d_mean_src[col] = sS * (1.0f / (float)BB);
            d_mean_trg[col] = sT * (1.0f / (float)BB);
        }
    }
    grid_barrier();

    // ===== P2: u1 (register-v row dots + butterfly) + colsum(u1) partials =====
    {
        const int c = t * 8;
        float vreg[8];
        *reinterpret_cast<float4*>(vreg)     = __ldcg(reinterpret_cast<const float4*>(d_v + c));
        *reinterpret_cast<float4*>(vreg + 4) = __ldcg(reinterpret_cast<const float4*>(d_v + c + 4));

        float acc[32];
#pragma unroll 8
        for (int r = 0; r < RPC; ++r) {
            uint2 raw = *reinterpret_cast<const uint2*>(g8 + r * NN + c);
            float f[8];
            fp8x4_to_f32(raw.x, f);
            fp8x4_to_f32(raw.y, f + 4);
            acc[r] = f[0] * vreg[0] + f[1] * vreg[1] + f[2] * vreg[2] + f[3] * vreg[3]
                   + f[4] * vreg[4] + f[5] * vreg[5] + f[6] * vreg[6] + f[7] * vreg[7];
        }
        float rowdot = bfly_reduce32(acc, l);
        wpart[w * 32 + l] = rowdot;
        __syncthreads();
        if (t < 32) {
            float s = 0.f;
#pragma unroll
            for (int w2 = 0; w2 < 16; ++w2) s += wpart[w2 * 32 + t];
            ush[t] = 1.0f / s;
        }
        __syncthreads();

        // colsum(u1): thread owns 8 columns over 32 rows
        float ca[8] = {0.f, 0.f, 0.f, 0.f, 0.f, 0.f, 0.f, 0.f};
#pragma unroll 8
        for (int r = 0; r < RPC; ++r) {
            float u = ush[r];
            uint2 raw = *reinterpret_cast<const uint2*>(g8 + r * NN + c);
            float f[8];
            fp8x4_to_f32(raw.x, f);
            fp8x4_to_f32(raw.y, f + 4);
#pragma unroll
            for (int k = 0; k < 8; ++k) ca[k] += u * f[k];
        }
        float* dst = d_colpart + (size_t)b * NN + c;
        *reinterpret_cast<float4*>(dst)     = make_float4(ca[0], ca[1], ca[2], ca[3]);
        *reinterpret_cast<float4*>(dst + 4) = make_float4(ca[4], ca[5], ca[6], ca[7]);
    }
    grid_barrier();

    // ===== P3: reduce -> v2 =====
    {
        int col = b * 32 + (t >> 4);
        int s   = t & 15;
        float sum = 0.f;
#pragma unroll
        for (int k = 0; k < 8; ++k)
            sum += __ldcg(d_colpart + (size_t)(s * 8 + k) * NN + col);
#pragma unroll
        for (int off = 8; off; off >>= 1) sum += __shfl_down_sync(0xffffffffu, sum, off, 16);
        if (s == 0) d_v[col] = 1.0f / sum;
    }
    grid_barrier();

    // ===== P4: exact row-normalize + loss (register v/ms + butterfly) =====
    {
        const int c = t * 8;
        float vreg[8], msreg[8];
        *reinterpret_cast<float4*>(vreg)      = __ldcg(reinterpret_cast<const float4*>(d_v + c));
        *reinterpret_cast<float4*>(vreg + 4)  = __ldcg(reinterpret_cast<const float4*>(d_v + c + 4));
        *reinterpret_cast<float4*>(msreg)     = __ldcg(reinterpret_cast<const float4*>(d_mean_src + c));
        *reinterpret_cast<float4*>(msreg + 4) = __ldcg(reinterpret_cast<const float4*>(d_mean_src + c + 4));
        if (t < 32) mtr[t] = __ldcg(d_mean_trg + r0 + t);
        __syncthreads();

        float loss_acc = 0.f;
#pragma unroll
        for (int ch = 0; ch < 2; ++ch) {
            float att[16], aww[16];
#pragma unroll 4
            for (int r16 = 0; r16 < 16; ++r16) {
                int r = ch * 16 + r16;
                uint2 raw = *reinterpret_cast<const uint2*>(g8 + r * NN + c);
                float f[8];
                fp8x4_to_f32(raw.x, f);
                fp8x4_to_f32(raw.y, f + 4);
                float mt = mtr[r];
                float at = 0.f, aw = 0.f;
#pragma unroll
                for (int k = 0; k < 8; ++k) {
                    float gv = f[k] * vreg[k];
                    at += gv;
                    aw += fabsf(mt - msreg[k]) * gv;
                }
                att[r16] = at;
                aww[r16] = aw;
            }
            float atf = bfly_reduce16(att, l);
            float awf = bfly_reduce16(aww, l);
            if (l < 16) {
                redT[w * 16 + l] = atf;
                redW[w * 16 + l] = awf;
            }
            __syncthreads();
            if (t < 16) {
                float at = 0.f, aw = 0.f;
#pragma unroll
                for (int w2 = 0; w2 < 16; ++w2) {
                    at += redT[w2 * 16 + t];
                    aw += redW[w2 * 16 + t];
                }
                loss_acc += aw / at;
            }
            __syncthreads();
        }
        if (t < 16) {
#pragma unroll
            for (int off = 8; off; off >>= 1)
                loss_acc += __shfl_down_sync(0x0000ffffu, loss_acc, off, 16);
            if (t == 0) d_ctapart[b] = loss_acc;
        }
    }
    grid_barrier();

    // ===== P5: CTA 0 reduces 128 partials =====
    if (b == 0 && t < 32) {
        float s = 0.f;
#pragma unroll
        for (int k = 0; k < NCTA / 32; ++k) s += __ldcg(d_ctapart + t + 32 * k);
#pragma unroll
        for (int off = 16; off; off >>= 1) s += __shfl_down_sync(0xffffffffu, s, off);
        if (t == 0) out[0] = s;
    }
}

// ---------------------------------------------------------------------------
extern "C" void kernel_launch(void* const* d_in, const int* in_sizes, int n_in,
                              void* d_out, int out_size) {
    (void)in_sizes; (void)n_in; (void)out_size;
    const float* src = (const float*)d_in[0];
    const float* trg = (const float*)d_in[1];
    const float* G   = (const float*)d_in[2];
    float* out = (float*)d_out;

    cudaFuncSetAttribute(k_fused, cudaFuncAttributeMaxDynamicSharedMemorySize, SM_TOT);
    k_fused<<<NCTA, THREADS, SM_TOT>>>(src, trg, G, out);
}